// round 15
// baseline (speedup 1.0000x reference)
#include <cuda_runtime.h>
#include <cuda_fp16.h>
#include <cstdint>

// ==================== constants ====================
#define BSZ    8192
#define HDIM   1024
#define KTOT   2048           // I + H
#define BTILE  128            // batch rows per CTA
#define HT     32             // h-cols per CTA (per gate)
#define KC     64             // K per chunk (4 x k16 steps)
#define NCHUNK (KTOT / KC)    // 32
#define NSTEPS (NCHUNK * 4)   // 128 k16 steps
#define NTHREADS 256
#define CMOFF  ((size_t)BSZ * HDIM)

// fragment-packed fp16 scratch, uint4 (16B) slots  (R10 layout)
// A: [bb 64][kc 32][mtg 8][ks 4][lane 32]  = 2M slots (32MB)
// W: [g 4][hb 32][kc 32][ntp 2][ks 4][lane 32] = 1M slots (16MB)
#define A_SLOTS ((size_t)64 * 32 * 8 * 4 * 32)
#define W_SLOTS ((size_t)4 * 32 * 32 * 2 * 4 * 32)
__device__ uint4 g_scr[A_SLOTS + W_SLOTS];

// smem: epilogue gate-exchange only (4 planes of 128x32 f32)
#define SMEM_BYTES 65536

#define PITCH_H 68   // padded halves per smem row in prep tiles

// ==================== helpers ====================
__device__ __forceinline__ void mma_f16(float* d, const uint4& a, uint32_t b0, uint32_t b1) {
    asm volatile(
        "mma.sync.aligned.m16n8k16.row.col.f32.f16.f16.f32 "
        "{%0,%1,%2,%3}, {%4,%5,%6,%7}, {%8,%9}, {%0,%1,%2,%3};"
        : "+f"(d[0]), "+f"(d[1]), "+f"(d[2]), "+f"(d[3])
        : "r"(a.x), "r"(a.y), "r"(a.z), "r"(a.w), "r"(b0), "r"(b1));
}
__device__ __forceinline__ float sigm(float z) {
    return __fdividef(1.0f, 1.0f + __expf(-z));
}
__device__ __forceinline__ float tanh_(float z) {
    float e = __expf(-2.0f * z);
    return (1.0f - e) * __fdividef(1.0f, 1.0f + e);
}

// ==================== prep: tiled, coalesced convert + fragment pack ====================
// Blocks 0..2047: A tiles (bb = blk>>5, kc = blk&31): 128 rows x 64 cols.
// Blocks 2048..6143: W tiles (g, hb, kc): 32 rows x 64 cols.
__global__ void __launch_bounds__(256) prep_kernel(
    const float* __restrict__ x, const float* __restrict__ h,
    const float* __restrict__ Wxi, const float* __restrict__ Whi,
    const float* __restrict__ Wxf, const float* __restrict__ Whf,
    const float* __restrict__ Wxc, const float* __restrict__ Whc,
    const float* __restrict__ Wxo, const float* __restrict__ Who)
{
    __shared__ __half sh[128 * PITCH_H];
    const int blk = blockIdx.x;
    const int tid = threadIdx.x;

    if (blk < 2048) {
        const int bb = blk >> 5, kc = blk & 31;
        #pragma unroll
        for (int t = 0; t < 8; t++) {
            const int idx = t * 256 + tid;        // 0..2047 float4
            const int r = idx >> 4, c4 = idx & 15;
            const int gr = bb * 128 + r;
            const int gc = kc * 64 + c4 * 4;
            const float* S = (gc < 1024) ? x : h;
            const int cc = (gc < 1024) ? gc : gc - 1024;
            float4 v = *(const float4*)(S + (size_t)gr * 1024 + cc);
            __half2* dst = (__half2*)(sh + r * PITCH_H + c4 * 4);
            dst[0] = __floats2half2_rn(v.x, v.y);
            dst[1] = __floats2half2_rn(v.z, v.w);
        }
        __syncthreads();
        #pragma unroll
        for (int t = 0; t < 4; t++) {
            const int s = t * 256 + tid;          // [mtg 8][ks 4][lane 32]
            const int lane = s & 31, ks = (s >> 5) & 3, mtg = s >> 7;
            const int gid = lane >> 2, tg = lane & 3;
            const int r0 = mtg * 16 + gid;
            const int c  = ks * 16 + 2 * tg;
            uint4 v;
            v.x = *(const uint32_t*)(sh + r0 * PITCH_H + c);
            v.y = *(const uint32_t*)(sh + (r0 + 8) * PITCH_H + c);
            v.z = *(const uint32_t*)(sh + r0 * PITCH_H + c + 8);
            v.w = *(const uint32_t*)(sh + (r0 + 8) * PITCH_H + c + 8);
            g_scr[(size_t)(bb * 32 + kc) * 1024 + s] = v;
        }
    } else {
        const int i2 = blk - 2048;                // 0..4095
        const int g = i2 >> 10, hb = (i2 >> 5) & 31, kc = i2 & 31;
        const float* wx = (g == 0) ? Wxi : (g == 1) ? Wxf : (g == 2) ? Wxc : Wxo;
        const float* wh = (g == 0) ? Whi : (g == 1) ? Whf : (g == 2) ? Whc : Who;
        #pragma unroll
        for (int t = 0; t < 2; t++) {
            const int idx = t * 256 + tid;        // 0..511 float4
            const int r = idx >> 4, c4 = idx & 15;
            const int gr = hb * 32 + r;
            const int gc = kc * 64 + c4 * 4;
            const float* S = (gc < 1024) ? wx : wh;
            const int cc = (gc < 1024) ? gc : gc - 1024;
            float4 v = *(const float4*)(S + (size_t)gr * 1024 + cc);
            __half2* dst = (__half2*)(sh + r * PITCH_H + c4 * 4);
            dst[0] = __floats2half2_rn(v.x, v.y);
            dst[1] = __floats2half2_rn(v.z, v.w);
        }
        __syncthreads();
        {
            const int s = tid;                    // [ntp 2][ks 4][lane 32]
            const int lane = s & 31, ks = (s >> 5) & 3, ntp = s >> 7;
            const int gid = lane >> 2, tg = lane & 3;
            const int n0 = ntp * 16 + gid;
            const int c  = ks * 16 + 2 * tg;
            uint4 v;
            v.x = *(const uint32_t*)(sh + n0 * PITCH_H + c);
            v.y = *(const uint32_t*)(sh + n0 * PITCH_H + c + 8);
            v.z = *(const uint32_t*)(sh + (n0 + 8) * PITCH_H + c);
            v.w = *(const uint32_t*)(sh + (n0 + 8) * PITCH_H + c + 8);
            g_scr[A_SLOTS + (((size_t)g * 32 + hb) * 32 + kc) * 256 + s] = v;
        }
    }
}

// ==================== fragment loader (one k16 step) ====================
__device__ __forceinline__ void load_frags(const uint4* __restrict__ Aw,
                                           const uint4* __restrict__ Ww,
                                           int s, uint4 av[4], uint4 bv[2]) {
    const int kc = s >> 2, ks = s & 3;
    const uint4* __restrict__ Ak = Aw + (size_t)kc * 1024 + ks * 32;
    const uint4* __restrict__ Wk = Ww + (size_t)kc * 256 + ks * 32;
    #pragma unroll
    for (int mt = 0; mt < 4; mt++) av[mt] = Ak[mt * 128];
    #pragma unroll
    for (int ntp = 0; ntp < 2; ntp++) bv[ntp] = Wk[ntp * 128];
}

// ==================== main fused LSTM: free-running, ks-level double buffer ====================
__global__ void __launch_bounds__(NTHREADS, 2) lstm_fused(
    const float* __restrict__ c_prev,
    const float* __restrict__ bxi, const float* __restrict__ bhi,
    const float* __restrict__ bxf, const float* __restrict__ bhf,
    const float* __restrict__ bxc, const float* __restrict__ bhc,
    const float* __restrict__ bxo, const float* __restrict__ bho,
    float* __restrict__ out)
{
    extern __shared__ float smf[];

    const int tid   = threadIdx.x;
    const int wid   = tid >> 5;
    const int lane  = tid & 31;
    const int gid   = lane >> 2;
    const int tg    = lane & 3;
    const int warp_m = wid >> 2;   // 0..1 (64 rows each)
    const int warp_n = wid & 3;    // 0..3 == gate

    const int hb = blockIdx.x;           // 0..31
    const int bb = blockIdx.y;           // 0..63
    const int h0 = hb * HT;
    const int b0 = bb * BTILE;

    const uint4* __restrict__ Awarp = g_scr
        + (size_t)bb * 32 * 1024
        + (size_t)(warp_m * 4) * 128 + lane;
    const uint4* __restrict__ Wwarp = g_scr + A_SLOTS
        + ((size_t)warp_n * 32 + hb) * 32 * 256 + lane;

    float acc[4][4][4];
    #pragma unroll
    for (int a = 0; a < 4; a++)
        #pragma unroll
        for (int b = 0; b < 4; b++)
            #pragma unroll
            for (int c = 0; c < 4; c++) acc[a][b][c] = 0.0f;

    uint4 av[2][4], bv[2][2];
    load_frags(Awarp, Wwarp, 0, av[0], bv[0]);

    #pragma unroll 2
    for (int s = 0; s < NSTEPS; s++) {
        const int cur = s & 1;
        if (s + 1 < NSTEPS)
            load_frags(Awarp, Wwarp, s + 1, av[cur ^ 1], bv[cur ^ 1]);
        #pragma unroll
        for (int mt = 0; mt < 4; mt++) {
            #pragma unroll
            for (int ntp = 0; ntp < 2; ntp++) {
                mma_f16(acc[mt][2 * ntp],     av[cur][mt], bv[cur][ntp].x, bv[cur][ntp].y);
                mma_f16(acc[mt][2 * ntp + 1], av[cur][mt], bv[cur][ntp].z, bv[cur][ntp].w);
            }
        }
    }

    // ---------- epilogue: gate exchange through smem ----------
    {
        float* ep = smf + warp_n * 4096;   // plane [128][32]
        #pragma unroll
        for (int mt = 0; mt < 4; mt++) {
            #pragma unroll
            for (int nt = 0; nt < 4; nt++) {
                const int r = warp_m * 64 + mt * 16 + gid;
                const int c = nt * 8 + 2 * tg;
                *(float2*)(ep + r * 32 + c)       = make_float2(acc[mt][nt][0], acc[mt][nt][1]);
                *(float2*)(ep + (r + 8) * 32 + c) = make_float2(acc[mt][nt][2], acc[mt][nt][3]);
            }
        }
    }
    __syncthreads();

    {
        const int col = tid & 31;
        const int grp = tid >> 5;
        const int h   = h0 + col;
        const float bi  = bxi[h] + bhi[h];
        const float bfv = bxf[h] + bhf[h];
        const float bc  = bxc[h] + bhc[h];
        const float bo  = bxo[h] + bho[h];
        const float* ep = smf;

        #pragma unroll
        for (int j = 0; j < 16; j++) {
            const int r  = grp * 16 + j;
            const int gb = b0 + r;
            const int o_ = r * 32 + col;
            const float zi = ep[o_]         + bi;
            const float zf = ep[4096 + o_]  + bfv;
            const float zc = ep[8192 + o_]  + bc;
            const float zo = ep[12288 + o_] + bo;
            const float iv = sigm(zi), fv = sigm(zf);
            const float gv = tanh_(zc), ov = sigm(zo);
            const float cp = c_prev[(size_t)gb * 1024 + h];
            const float cn = fv * cp + iv * gv;
            out[(size_t)gb * 1024 + h]         = ov * tanh_(cn);
            out[CMOFF + (size_t)gb * 1024 + h] = cn;
        }
    }
}

// ==================== launch ====================
extern "C" void kernel_launch(void* const* d_in, const int* in_sizes, int n_in,
                              void* d_out, int out_size) {
    const float* x      = (const float*)d_in[0];
    const float* h_prev = (const float*)d_in[1];
    const float* c_prev = (const float*)d_in[2];
    const float* Wxi = (const float*)d_in[3];
    const float* Whi = (const float*)d_in[4];
    const float* Wxf = (const float*)d_in[5];
    const float* Whf = (const float*)d_in[6];
    const float* Wxc = (const float*)d_in[7];
    const float* Whc = (const float*)d_in[8];
    const float* Wxo = (const float*)d_in[9];
    const float* Who = (const float*)d_in[10];
    const float* bxi = (const float*)d_in[11];
    const float* bhi = (const float*)d_in[12];
    const float* bxf = (const float*)d_in[13];
    const float* bhf = (const float*)d_in[14];
    const float* bxc = (const float*)d_in[15];
    const float* bhc = (const float*)d_in[16];
    const float* bxo = (const float*)d_in[17];
    const float* bho = (const float*)d_in[18];
    float* out = (float*)d_out;

    cudaFuncSetAttribute(lstm_fused, cudaFuncAttributeMaxDynamicSharedMemorySize, SMEM_BYTES);

    prep_kernel<<<6144, 256>>>(x, h_prev,
        Wxi, Whi, Wxf, Whf, Wxc, Whc, Wxo, Who);

    dim3 grid(HDIM / HT, BSZ / BTILE);   // (32, 64) = 2048 CTAs
    lstm_fused<<<grid, NTHREADS, SMEM_BYTES>>>(
        c_prev,
        bxi, bhi, bxf, bhf, bxc, bhc, bxo, bho,
        out);
}

// round 16
// speedup vs baseline: 1.0263x; 1.0263x over previous
#include <cuda_runtime.h>
#include <cuda_fp16.h>
#include <cstdint>

// ==================== constants ====================
#define BSZ    8192
#define HDIM   1024
#define KTOT   2048           // I + H
#define BTILE  128            // batch rows per CTA
#define HT     32             // h-cols per CTA (per gate)
#define KC     64             // K per chunk (4 x k16 steps)
#define NCHUNK (KTOT / KC)    // 32
#define NTHREADS 256
#define CMOFF  ((size_t)BSZ * HDIM)

// fragment-packed fp16 scratch, uint4 (16B) slots  (R10 layout)
// A: [bb 64][kc 32][mtg 8][ks 4][lane 32]  = 2M slots (32MB)
// W: [g 4][hb 32][kc 32][ntp 2][ks 4][lane 32] = 1M slots (16MB)
#define A_SLOTS ((size_t)64 * 32 * 8 * 4 * 32)
#define W_SLOTS ((size_t)4 * 32 * 32 * 2 * 4 * 32)
__device__ uint4 g_scr[A_SLOTS + W_SLOTS];

// smem: epilogue gate-exchange only (4 planes of 128x32 f32)
#define SMEM_BYTES 65536

#define PITCH_H 68   // padded halves per smem row in prep tiles

// ==================== helpers ====================
__device__ __forceinline__ void mma_f16(float* d, const uint4& a, uint32_t b0, uint32_t b1) {
    asm volatile(
        "mma.sync.aligned.m16n8k16.row.col.f32.f16.f16.f32 "
        "{%0,%1,%2,%3}, {%4,%5,%6,%7}, {%8,%9}, {%0,%1,%2,%3};"
        : "+f"(d[0]), "+f"(d[1]), "+f"(d[2]), "+f"(d[3])
        : "r"(a.x), "r"(a.y), "r"(a.z), "r"(a.w), "r"(b0), "r"(b1));
}
__device__ __forceinline__ float sigm(float z) {
    return __fdividef(1.0f, 1.0f + __expf(-z));
}
__device__ __forceinline__ float tanh_(float z) {
    float e = __expf(-2.0f * z);
    return (1.0f - e) * __fdividef(1.0f, 1.0f + e);
}

// ==================== prep: tiled, coalesced convert + fragment pack (R15, kept) ====================
// Blocks 0..2047: A tiles (bb = blk>>5, kc = blk&31): 128 rows x 64 cols.
// Blocks 2048..6143: W tiles (g, hb, kc): 32 rows x 64 cols.
__global__ void __launch_bounds__(256) prep_kernel(
    const float* __restrict__ x, const float* __restrict__ h,
    const float* __restrict__ Wxi, const float* __restrict__ Whi,
    const float* __restrict__ Wxf, const float* __restrict__ Whf,
    const float* __restrict__ Wxc, const float* __restrict__ Whc,
    const float* __restrict__ Wxo, const float* __restrict__ Who)
{
    __shared__ __half sh[128 * PITCH_H];
    const int blk = blockIdx.x;
    const int tid = threadIdx.x;

    if (blk < 2048) {
        const int bb = blk >> 5, kc = blk & 31;
        #pragma unroll
        for (int t = 0; t < 8; t++) {
            const int idx = t * 256 + tid;        // 0..2047 float4
            const int r = idx >> 4, c4 = idx & 15;
            const int gr = bb * 128 + r;
            const int gc = kc * 64 + c4 * 4;
            const float* S = (gc < 1024) ? x : h;
            const int cc = (gc < 1024) ? gc : gc - 1024;
            float4 v = *(const float4*)(S + (size_t)gr * 1024 + cc);
            __half2* dst = (__half2*)(sh + r * PITCH_H + c4 * 4);
            dst[0] = __floats2half2_rn(v.x, v.y);
            dst[1] = __floats2half2_rn(v.z, v.w);
        }
        __syncthreads();
        #pragma unroll
        for (int t = 0; t < 4; t++) {
            const int s = t * 256 + tid;          // [mtg 8][ks 4][lane 32]
            const int lane = s & 31, ks = (s >> 5) & 3, mtg = s >> 7;
            const int gid = lane >> 2, tg = lane & 3;
            const int r0 = mtg * 16 + gid;
            const int c  = ks * 16 + 2 * tg;
            uint4 v;
            v.x = *(const uint32_t*)(sh + r0 * PITCH_H + c);
            v.y = *(const uint32_t*)(sh + (r0 + 8) * PITCH_H + c);
            v.z = *(const uint32_t*)(sh + r0 * PITCH_H + c + 8);
            v.w = *(const uint32_t*)(sh + (r0 + 8) * PITCH_H + c + 8);
            g_scr[(size_t)(bb * 32 + kc) * 1024 + s] = v;
        }
    } else {
        const int i2 = blk - 2048;                // 0..4095
        const int g = i2 >> 10, hb = (i2 >> 5) & 31, kc = i2 & 31;
        const float* wx = (g == 0) ? Wxi : (g == 1) ? Wxf : (g == 2) ? Wxc : Wxo;
        const float* wh = (g == 0) ? Whi : (g == 1) ? Whf : (g == 2) ? Whc : Who;
        #pragma unroll
        for (int t = 0; t < 2; t++) {
            const int idx = t * 256 + tid;        // 0..511 float4
            const int r = idx >> 4, c4 = idx & 15;
            const int gr = hb * 32 + r;
            const int gc = kc * 64 + c4 * 4;
            const float* S = (gc < 1024) ? wx : wh;
            const int cc = (gc < 1024) ? gc : gc - 1024;
            float4 v = *(const float4*)(S + (size_t)gr * 1024 + cc);
            __half2* dst = (__half2*)(sh + r * PITCH_H + c4 * 4);
            dst[0] = __floats2half2_rn(v.x, v.y);
            dst[1] = __floats2half2_rn(v.z, v.w);
        }
        __syncthreads();
        {
            const int s = tid;                    // [ntp 2][ks 4][lane 32]
            const int lane = s & 31, ks = (s >> 5) & 3, ntp = s >> 7;
            const int gid = lane >> 2, tg = lane & 3;
            const int n0 = ntp * 16 + gid;
            const int c  = ks * 16 + 2 * tg;
            uint4 v;
            v.x = *(const uint32_t*)(sh + n0 * PITCH_H + c);
            v.y = *(const uint32_t*)(sh + n0 * PITCH_H + c + 8);
            v.z = *(const uint32_t*)(sh + (n0 + 8) * PITCH_H + c);
            v.w = *(const uint32_t*)(sh + (n0 + 8) * PITCH_H + c + 8);
            g_scr[A_SLOTS + (((size_t)g * 32 + hb) * 32 + kc) * 256 + s] = v;
        }
    }
}

// ==================== main fused LSTM: R14 mainloop (free-running, implicit unroll-2) ====================
__global__ void __launch_bounds__(NTHREADS, 2) lstm_fused(
    const float* __restrict__ c_prev,
    const float* __restrict__ bxi, const float* __restrict__ bhi,
    const float* __restrict__ bxf, const float* __restrict__ bhf,
    const float* __restrict__ bxc, const float* __restrict__ bhc,
    const float* __restrict__ bxo, const float* __restrict__ bho,
    float* __restrict__ out)
{
    extern __shared__ float smf[];

    const int tid   = threadIdx.x;
    const int wid   = tid >> 5;
    const int lane  = tid & 31;
    const int gid   = lane >> 2;
    const int tg    = lane & 3;
    const int warp_m = wid >> 2;   // 0..1 (64 rows each)
    const int warp_n = wid & 3;    // 0..3 == gate

    const int hb = blockIdx.x;           // 0..31
    const int bb = blockIdx.y;           // 0..63
    const int h0 = hb * HT;
    const int b0 = bb * BTILE;

    // per-warp fragment base pointers into the packed scratch
    const uint4* __restrict__ Awarp = g_scr
        + (size_t)bb * 32 * 1024
        + (size_t)(warp_m * 4) * 128 + lane;
    const uint4* __restrict__ Wwarp = g_scr + A_SLOTS
        + ((size_t)warp_n * 32 + hb) * 32 * 256 + lane;

    float acc[4][4][4];
    #pragma unroll
    for (int a = 0; a < 4; a++)
        #pragma unroll
        for (int b = 0; b < 4; b++)
            #pragma unroll
            for (int c = 0; c < 4; c++) acc[a][b][c] = 0.0f;

    #pragma unroll 2
    for (int kc = 0; kc < NCHUNK; kc++) {
        const uint4* __restrict__ Ak = Awarp + (size_t)kc * 1024;
        const uint4* __restrict__ Wk = Wwarp + (size_t)kc * 256;

        #pragma unroll
        for (int ks = 0; ks < 4; ks++) {
            uint4 av[4], bv[2];
            #pragma unroll
            for (int mt = 0; mt < 4; mt++)
                av[mt] = Ak[(mt * 4 + ks) * 32];
            #pragma unroll
            for (int ntp = 0; ntp < 2; ntp++)
                bv[ntp] = Wk[(ntp * 4 + ks) * 32];
            #pragma unroll
            for (int mt = 0; mt < 4; mt++) {
                #pragma unroll
                for (int ntp = 0; ntp < 2; ntp++) {
                    mma_f16(acc[mt][2 * ntp],     av[mt], bv[ntp].x, bv[ntp].y);
                    mma_f16(acc[mt][2 * ntp + 1], av[mt], bv[ntp].z, bv[ntp].w);
                }
            }
        }
        // no synchronization: warps free-run; scoreboard covers L1/L2 latency
    }

    // ---------- epilogue: gate exchange through smem ----------
    {
        float* ep = smf + warp_n * 4096;   // plane [128][32]
        #pragma unroll
        for (int mt = 0; mt < 4; mt++) {
            #pragma unroll
            for (int nt = 0; nt < 4; nt++) {
                const int r = warp_m * 64 + mt * 16 + gid;
                const int c = nt * 8 + 2 * tg;
                *(float2*)(ep + r * 32 + c)       = make_float2(acc[mt][nt][0], acc[mt][nt][1]);
                *(float2*)(ep + (r + 8) * 32 + c) = make_float2(acc[mt][nt][2], acc[mt][nt][3]);
            }
        }
    }
    __syncthreads();

    {
        const int col = tid & 31;
        const int grp = tid >> 5;
        const int h   = h0 + col;
        const float bi  = bxi[h] + bhi[h];
        const float bfv = bxf[h] + bhf[h];
        const float bc  = bxc[h] + bhc[h];
        const float bo  = bxo[h] + bho[h];
        const float* ep = smf;

        #pragma unroll
        for (int j = 0; j < 16; j++) {
            const int r  = grp * 16 + j;
            const int gb = b0 + r;
            const int o_ = r * 32 + col;
            const float zi = ep[o_]         + bi;
            const float zf = ep[4096 + o_]  + bfv;
            const float zc = ep[8192 + o_]  + bc;
            const float zo = ep[12288 + o_] + bo;
            const float iv = sigm(zi), fv = sigm(zf);
            const float gv = tanh_(zc), ov = sigm(zo);
            const float cp = c_prev[(size_t)gb * 1024 + h];
            const float cn = fv * cp + iv * gv;
            out[(size_t)gb * 1024 + h]         = ov * tanh_(cn);
            out[CMOFF + (size_t)gb * 1024 + h] = cn;
        }
    }
}

// ==================== launch ====================
extern "C" void kernel_launch(void* const* d_in, const int* in_sizes, int n_in,
                              void* d_out, int out_size) {
    const float* x      = (const float*)d_in[0];
    const float* h_prev = (const float*)d_in[1];
    const float* c_prev = (const float*)d_in[2];
    const float* Wxi = (const float*)d_in[3];
    const float* Whi = (const float*)d_in[4];
    const float* Wxf = (const float*)d_in[5];
    const float* Whf = (const float*)d_in[6];
    const float* Wxc = (const float*)d_in[7];
    const float* Whc = (const float*)d_in[8];
    const float* Wxo = (const float*)d_in[9];
    const float* Who = (const float*)d_in[10];
    const float* bxi = (const float*)d_in[11];
    const float* bhi = (const float*)d_in[12];
    const float* bxf = (const float*)d_in[13];
    const float* bhf = (const float*)d_in[14];
    const float* bxc = (const float*)d_in[15];
    const float* bhc = (const float*)d_in[16];
    const float* bxo = (const float*)d_in[17];
    const float* bho = (const float*)d_in[18];
    float* out = (float*)d_out;

    cudaFuncSetAttribute(lstm_fused, cudaFuncAttributeMaxDynamicSharedMemorySize, SMEM_BYTES);

    prep_kernel<<<6144, 256>>>(x, h_prev,
        Wxi, Whi, Wxf, Whf, Wxc, Whc, Wxo, Who);

    dim3 grid(HDIM / HT, BSZ / BTILE);   // (32, 64) = 2048 CTAs
    lstm_fused<<<grid, NTHREADS, SMEM_BYTES>>>(
        c_prev,
        bxi, bhi, bxf, bhf, bxc, bhc, bxo, bho,
        out);
}